// round 4
// baseline (speedup 1.0000x reference)
#include <cuda_runtime.h>

typedef unsigned long long u64;

#define LOG2E 1.4426950408889634f
#define LN2   0.6931471805599453f
#define B    512
#define TT   1024
#define L    48

__device__ float g_fwd[B];
__device__ float g_gold[B];

static __device__ __forceinline__ u64 pk2(float lo, float hi){ u64 r; asm("mov.b64 %0, {%1, %2};" : "=l"(r) : "f"(lo), "f"(hi)); return r; }
static __device__ __forceinline__ u64 fma2(u64 a, u64 b, u64 c){ u64 d; asm("fma.rn.f32x2 %0, %1, %2, %3;" : "=l"(d) : "l"(a), "l"(b), "l"(c)); return d; }
static __device__ __forceinline__ u64 mul2(u64 a, u64 b){ u64 d; asm("mul.rn.f32x2 %0, %1, %2;" : "=l"(d) : "l"(a), "l"(b)); return d; }
static __device__ __forceinline__ u64 add2(u64 a, u64 b){ u64 d; asm("add.rn.f32x2 %0, %1, %2;" : "=l"(d) : "l"(a), "l"(b)); return d; }
static __device__ __forceinline__ float ex2f(float x){ float y; asm("ex2.approx.ftz.f32 %0, %1;" : "=f"(y) : "f"(x)); return y; }
static __device__ __forceinline__ float lg2f(float x){ float y; asm("lg2.approx.ftz.f32 %0, %1;" : "=f"(y) : "f"(x)); return y; }

// ---------------------------------------------------------------------------
// Forward kernel: 256 blocks x 64 threads. Block owns 2 sequences packed
// into f32x2 lanes. Thread j (j<48) owns label j: full 48-FMA2 dot per step.
// Emissions/masks: per-thread 8-deep register LDG pipeline (coalesced).
// State exchange: smem ping-pong + one 2-warp __syncthreads per step.
// Renorm: every 4 steps by 2^-exponent(u[0]) (exact, ~12 instr).
// ---------------------------------------------------------------------------
__global__ __launch_bounds__(64) void crf_fwd_kernel(
    const float* __restrict__ em, const int* __restrict__ mask,
    const float* __restrict__ trans, const float* __restrict__ startt,
    const float* __restrict__ endt)
{
    __shared__ __align__(16) u64 sh_u[2][64];   // ping-pong state (48 used)

    const int j   = threadIdx.x;
    const bool active = j < L;
    const int bA  = blockIdx.x * 2;
    const int bB  = bA + 1;

    // --- transition matrix column j, exponentiated, splatted into 48 u64 regs
    u64 et[L];
    float expEnd = 0.f;
    if (active) {
        #pragma unroll
        for (int i = 0; i < L; i++) {
            float e = ex2f(trans[i * L + j] * LOG2E);
            et[i] = pk2(e, e);
        }
        expEnd = ex2f(endt[j] * LOG2E);
    }

    // --- initial state u0 = exp(start + em[0])
    u64 res = 0;
    if (active) {
        float sv = startt[j];
        float a = ex2f((sv + em[(size_t)bA * TT * L + j]) * LOG2E);
        float b = ex2f((sv + em[(size_t)bB * TT * L + j]) * LOG2E);
        res = pk2(a, b);
        sh_u[0][j] = res;
    }

    // --- emission/mask register pipeline, depth 8 (stage k holds step tb+k)
    const float* pA = em + (size_t)bA * TT * L + j;
    const float* pB = em + (size_t)bB * TT * L + j;
    const int*   mA = mask + bA * TT;
    const int*   mB = mask + bB * TT;

    float eA[8], eB[8];
    int   kA[8], kB[8];
    #pragma unroll
    for (int s = 0; s < 8; s++) {
        int tp = 1 + s;
        eA[s] = active ? pA[(size_t)tp * L] : 0.f;
        eB[s] = active ? pB[(size_t)tp * L] : 0.f;
        kA[s] = mA[tp];
        kB[s] = mB[tp];
    }
    __syncthreads();

    int iAlo = 0, iAhi = 0;   // accumulated log2-scale (exact integers)

    for (int tb = 1; tb < TT + 7; tb += 8) {
        #pragma unroll
        for (int k = 0; k < 8; k++) {
            const int t = tb + k;
            if (t < TT) {                      // uniform guard
                const int rb = (t - 1) & 1, wb = t & 1;
                const ulonglong2* up = reinterpret_cast<const ulonglong2*>(&sh_u[rb][0]);

                ulonglong2 v0 = up[0];
                u64 first = v0.x;              // u[t-1][0] pair (for renorm)
                u64 a0 = fma2(v0.x, et[0], 0);
                u64 a1 = fma2(v0.y, et[1], 0);
                ulonglong2 v1 = up[1];
                u64 a2 = fma2(v1.x, et[2], 0);
                u64 a3 = fma2(v1.y, et[3], 0);
                #pragma unroll
                for (int q = 1; q < 12; q++) {
                    ulonglong2 w0 = up[2 * q];
                    ulonglong2 w1 = up[2 * q + 1];
                    a0 = fma2(w0.x, et[4 * q + 0], a0);
                    a1 = fma2(w0.y, et[4 * q + 1], a1);
                    a2 = fma2(w1.x, et[4 * q + 2], a2);
                    a3 = fma2(w1.y, et[4 * q + 3], a3);
                }
                u64 dot = add2(add2(a0, a1), add2(a2, a3));

                // emissions (from stage k) + mask select
                u64 Ee = pk2(ex2f(eA[k] * LOG2E), ex2f(eB[k] * LOG2E));
                u64 prod = mul2(dot, Ee);
                unsigned mloA = kA[k] ? 0xFFFFFFFFu : 0u;
                unsigned mhiB = kB[k] ? 0xFFFFFFFFu : 0u;
                u64 mm = (u64)mloA | ((u64)mhiB << 32);
                u64 sel = (prod & mm) | (res & ~mm);

                if ((t & 3) == 0) {            // exact power-of-2 renorm
                    unsigned bLo = (unsigned)first;
                    unsigned bHi = (unsigned)(first >> 32);
                    unsigned eL = bLo & 0x7F800000u;
                    unsigned eH = bHi & 0x7F800000u;
                    float fL = __uint_as_float(0x7F000000u - eL);
                    float fH = __uint_as_float(0x7F000000u - eH);
                    sel = mul2(sel, pk2(fL, fH));
                    iAlo += (int)(eL >> 23) - 127;
                    iAhi += (int)(eH >> 23) - 127;
                }
                res = sel;
                if (active) sh_u[wb][j] = res;

                // refill stage k for step t+8
                const int tp2 = t + 8;
                if (tp2 < TT) {
                    if (active) {
                        eA[k] = pA[(size_t)tp2 * L];
                        eB[k] = pB[(size_t)tp2 * L];
                    }
                    kA[k] = mA[tp2];
                    kB[k] = mB[tp2];
                }
            }
            __syncthreads();
        }
    }

    // --- finalize: logZ = log2(sum_j u_j * exp(end_j)) + credits, * ln2
    if (active) sh_u[0][j] = mul2(res, pk2(expEnd, expEnd));
    __syncthreads();
    if (j < 2) {
        const float* base = ((const float*)&sh_u[0][0]) + j;  // j=0: lo, j=1: hi
        float s = 0.f;
        #pragma unroll
        for (int q = 0; q < L; q++) s += base[2 * q];
        int credit = j ? iAhi : iAlo;
        g_fwd[bA + j] = (lg2f(s) + (float)credit) * LN2;
    }
}

// ---------------------------------------------------------------------------
// Gold score kernel: one block per batch element.
// ---------------------------------------------------------------------------
__global__ __launch_bounds__(256, 4) void crf_gold_kernel(
    const float* __restrict__ em, const int* __restrict__ labels,
    const int* __restrict__ mask, const float* __restrict__ trans,
    const float* __restrict__ startt, const float* __restrict__ endt)
{
    __shared__ float red[256];
    __shared__ int   redc[256];
    const int b = blockIdx.x;
    const int tid = threadIdx.x;

    float acc = 0.f;
    int cnt = 0;
    for (int t = tid; t < TT; t += 256) {
        int l = labels[b * TT + t];
        int m = mask[b * TT + t];
        cnt += m;
        float e = em[((size_t)(b * TT) + t) * L + l];
        if (t == 0) {
            acc += startt[l] + e;
        } else {
            int lp = labels[b * TT + t - 1];
            acc += (e + trans[l * L + lp]) * (float)m;
        }
    }
    red[tid] = acc; redc[tid] = cnt;
    __syncthreads();
    for (int s = 128; s > 0; s >>= 1) {
        if (tid < s) { red[tid] += red[tid + s]; redc[tid] += redc[tid + s]; }
        __syncthreads();
    }
    if (tid == 0) {
        int len = redc[0] - 1;
        int last = labels[b * TT + len];
        g_gold[b] = red[0] + endt[last];
    }
}

// ---------------------------------------------------------------------------
// Final reduction: mean(fwd - gold)
// ---------------------------------------------------------------------------
__global__ __launch_bounds__(512, 1) void crf_final_kernel(float* __restrict__ out)
{
    __shared__ float red[512];
    int tid = threadIdx.x;
    red[tid] = g_fwd[tid] - g_gold[tid];
    __syncthreads();
    for (int s = 256; s > 0; s >>= 1) {
        if (tid < s) red[tid] += red[tid + s];
        __syncthreads();
    }
    if (tid == 0) out[0] = red[0] * (1.0f / (float)B);
}

extern "C" void kernel_launch(void* const* d_in, const int* in_sizes, int n_in,
                              void* d_out, int out_size)
{
    const float* em     = (const float*)d_in[0];
    const int*   labels = (const int*)  d_in[1];
    const int*   mask   = (const int*)  d_in[2];
    const float* trans  = (const float*)d_in[3];
    const float* startt = (const float*)d_in[4];
    const float* endt   = (const float*)d_in[5];
    float* out = (float*)d_out;

    crf_fwd_kernel<<<B / 2, 64>>>(em, mask, trans, startt, endt);
    crf_gold_kernel<<<B, 256>>>(em, labels, mask, trans, startt, endt);
    crf_final_kernel<<<1, 512>>>(out);
}

// round 5
// speedup vs baseline: 2.6664x; 2.6664x over previous
#include <cuda_runtime.h>

typedef unsigned long long u64;

#define LOG2E 1.4426950408889634f
#define LN2   0.6931471805599453f
#define B    512
#define TT   1024
#define L    48
#define RING 16   // cp.async emission ring slots (512B each)

__device__ float g_fwd[B];
__device__ float g_gold[B];

static __device__ __forceinline__ u64 pk2(float lo, float hi){ u64 r; asm("mov.b64 %0, {%1, %2};" : "=l"(r) : "f"(lo), "f"(hi)); return r; }
static __device__ __forceinline__ u64 fma2(u64 a, u64 b, u64 c){ u64 d; asm("fma.rn.f32x2 %0, %1, %2, %3;" : "=l"(d) : "l"(a), "l"(b), "l"(c)); return d; }
static __device__ __forceinline__ u64 mul2(u64 a, u64 b){ u64 d; asm("mul.rn.f32x2 %0, %1, %2;" : "=l"(d) : "l"(a), "l"(b)); return d; }
static __device__ __forceinline__ u64 add2(u64 a, u64 b){ u64 d; asm("add.rn.f32x2 %0, %1, %2;" : "=l"(d) : "l"(a), "l"(b)); return d; }
static __device__ __forceinline__ float ex2f(float x){ float y; asm("ex2.approx.ftz.f32 %0, %1;" : "=f"(y) : "f"(x)); return y; }
static __device__ __forceinline__ float lg2f(float x){ float y; asm("lg2.approx.ftz.f32 %0, %1;" : "=f"(y) : "f"(x)); return y; }
static __device__ __forceinline__ unsigned smem_u32(const void* p){
    unsigned a; asm("{ .reg .u64 t; cvta.to.shared.u64 t, %1; cvt.u32.u64 %0, t; }" : "=r"(a) : "l"(p)); return a; }

// ---------------------------------------------------------------------------
// Forward kernel: 256 blocks x 64 threads, 2 sequences per block packed into
// f32x2 lanes. Thread j owns label j (j>=48 shadow label 47, results unread).
// Emissions stream through a 16-slot smem ring filled by cp.async (LDGSTS):
// completion via commit_group/wait_group(14) => 15-step (~2000cyc) lookahead,
// no register-scoreboard exposure. Masks pre-packed into smem once.
// Renorm every 4 steps by exact power-of-2 from exponent(u[0]).
// ---------------------------------------------------------------------------
__global__ __launch_bounds__(64) void crf_fwd_kernel(
    const float* __restrict__ em, const int* __restrict__ mask,
    const float* __restrict__ trans, const float* __restrict__ startt,
    const float* __restrict__ endt)
{
    __shared__ __align__(16) u64   sh_u[2][64];        // ping-pong state
    __shared__ __align__(16) float sh_em[RING][128];   // ring: [0..47]=A, [64..111]=B
    __shared__ __align__(16) u64   sh_mm[TT];          // packed select masks (8KB)

    const int j  = threadIdx.x;
    const int jc = j < L ? j : (L - 1);                // clamp for shadow threads
    const int bA = blockIdx.x * 2, bB = bA + 1;

    // ---- pre-pack masks (once) ----
    for (int t = j; t < TT; t += 64) {
        unsigned a = mask[bA * TT + t] ? 0xFFFFFFFFu : 0u;
        unsigned b = mask[bB * TT + t] ? 0xFFFFFFFFu : 0u;
        sh_mm[t] = (u64)a | ((u64)b << 32);
    }

    // ---- transition column j, exponentiated, splatted ----
    u64 et[L];
    #pragma unroll
    for (int i = 0; i < L; i++) {
        float e = ex2f(trans[i * L + jc] * LOG2E);
        et[i] = pk2(e, e);
    }
    const float expEnd = ex2f(endt[jc] * LOG2E);

    // ---- initial state ----
    u64 res;
    {
        float sv = startt[jc];
        float a = ex2f((sv + em[(size_t)bA * TT * L + jc]) * LOG2E);
        float b = ex2f((sv + em[(size_t)bB * TT * L + jc]) * LOG2E);
        res = pk2(a, b);
        sh_u[0][j] = res;
    }

    // ---- cp.async producer setup: lanes 0..11 -> seq A, 12..23 -> seq B ----
    const float* gbase = (j < 12) ? (em + (size_t)bA * TT * L + j * 4)
                                  : (em + (size_t)bB * TT * L + (j - 12) * 4);
    const unsigned dst_off  = (j < 12) ? (unsigned)(j * 16) : (unsigned)(256 + (j - 12) * 16);
    const unsigned ring_base = smem_u32(&sh_em[0][0]);

    // prologue: fill slots 1..15 (one commit group per slot/row)
    for (int tp = 1; tp < RING; ++tp) {
        if (j < 24) {
            const float* src = gbase + (size_t)tp * L;
            unsigned d = ring_base + (unsigned)tp * 512u + dst_off;
            asm volatile("cp.async.cg.shared.global [%0], [%1], 16;" :: "r"(d), "l"(src));
        }
        asm volatile("cp.async.commit_group;");
    }
    asm volatile("cp.async.wait_group 14;");   // row 1 resident
    __syncthreads();

    int iAlo = 0, iAhi = 0;                    // exact integer log2 credits
    const u64* pr = sh_u[0];
    u64*       pw = sh_u[1];

    #pragma unroll 1
    for (int t = 1; t < TT; ++t) {
        // ---- 48x48 matvec (broadcast LDS of u, FMA2 into 4 accumulators) ----
        const ulonglong2* up = reinterpret_cast<const ulonglong2*>(pr);
        u64 a0 = 0, a1 = 0, a2 = 0, a3 = 0;
        u64 first = 0;
        #pragma unroll
        for (int q = 0; q < 12; q++) {
            ulonglong2 w0 = up[2 * q];
            ulonglong2 w1 = up[2 * q + 1];
            if (q == 0) first = w0.x;          // u[t-1][0] pair (renorm reference)
            a0 = fma2(w0.x, et[4 * q + 0], a0);
            a1 = fma2(w0.y, et[4 * q + 1], a1);
            a2 = fma2(w1.x, et[4 * q + 2], a2);
            a3 = fma2(w1.y, et[4 * q + 3], a3);
        }
        u64 dot = add2(add2(a0, a1), add2(a2, a3));

        // ---- emissions from ring + mask select ----
        const int slot = t & (RING - 1);
        float emA = sh_em[slot][jc];
        float emB = sh_em[slot][64 + jc];
        u64 Ee   = pk2(ex2f(emA * LOG2E), ex2f(emB * LOG2E));
        u64 prod = mul2(dot, Ee);
        u64 mm   = sh_mm[t];
        u64 sel  = (prod & mm) | (res & ~mm);

        if ((t & 3) == 0) {                    // exact power-of-2 renorm
            unsigned bLo = (unsigned)first, bHi = (unsigned)(first >> 32);
            unsigned eL = bLo & 0x7F800000u, eH = bHi & 0x7F800000u;
            sel = mul2(sel, pk2(__uint_as_float(0x7F000000u - eL),
                                __uint_as_float(0x7F000000u - eH)));
            iAlo += (int)(eL >> 23) - 127;
            iAhi += (int)(eH >> 23) - 127;
        }
        res = sel;
        pw[j] = res;

        // ---- refill ring slot for row t+15 (clamped; redundant dup is benign) ----
        {
            int tf = t + (RING - 1); if (tf > TT - 1) tf = TT - 1;
            if (j < 24) {
                const float* src = gbase + (size_t)tf * L;
                unsigned d = ring_base + (unsigned)(tf & (RING - 1)) * 512u + dst_off;
                asm volatile("cp.async.cg.shared.global [%0], [%1], 16;" :: "r"(d), "l"(src));
            }
            asm volatile("cp.async.commit_group;");
            asm volatile("cp.async.wait_group 14;");   // row t+1 resident
        }

        const u64* tmp = pr; pr = pw; pw = (u64*)tmp;
        __syncthreads();
    }

    // ---- finalize: logZ = (log2(sum_j u_j * exp(end_j)) + credit) * ln2 ----
    __syncthreads();
    sh_u[1][j] = mul2(res, pk2(expEnd, expEnd));       // res corresponds to pr buffer
    __syncthreads();
    if (j < 2) {
        const float* base = ((const float*)&sh_u[1][0]) + j;   // j=0: seqA, j=1: seqB
        float s = 0.f;
        #pragma unroll
        for (int q = 0; q < L; q++) s += base[2 * q];
        int credit = j ? iAhi : iAlo;
        g_fwd[bA + j] = (lg2f(s) + (float)credit) * LN2;
    }
}

// ---------------------------------------------------------------------------
// Gold score kernel: one block per batch element.
// ---------------------------------------------------------------------------
__global__ __launch_bounds__(256, 4) void crf_gold_kernel(
    const float* __restrict__ em, const int* __restrict__ labels,
    const int* __restrict__ mask, const float* __restrict__ trans,
    const float* __restrict__ startt, const float* __restrict__ endt)
{
    __shared__ float red[256];
    __shared__ int   redc[256];
    const int b = blockIdx.x;
    const int tid = threadIdx.x;

    float acc = 0.f;
    int cnt = 0;
    for (int t = tid; t < TT; t += 256) {
        int l = labels[b * TT + t];
        int m = mask[b * TT + t];
        cnt += m;
        float e = em[((size_t)(b * TT) + t) * L + l];
        if (t == 0) {
            acc += startt[l] + e;
        } else {
            int lp = labels[b * TT + t - 1];
            acc += (e + trans[l * L + lp]) * (float)m;
        }
    }
    red[tid] = acc; redc[tid] = cnt;
    __syncthreads();
    for (int s = 128; s > 0; s >>= 1) {
        if (tid < s) { red[tid] += red[tid + s]; redc[tid] += redc[tid + s]; }
        __syncthreads();
    }
    if (tid == 0) {
        int len = redc[0] - 1;
        int last = labels[b * TT + len];
        g_gold[b] = red[0] + endt[last];
    }
}

// ---------------------------------------------------------------------------
// Final reduction: mean(fwd - gold)
// ---------------------------------------------------------------------------
__global__ __launch_bounds__(512, 1) void crf_final_kernel(float* __restrict__ out)
{
    __shared__ float red[512];
    int tid = threadIdx.x;
    red[tid] = g_fwd[tid] - g_gold[tid];
    __syncthreads();
    for (int s = 256; s > 0; s >>= 1) {
        if (tid < s) red[tid] += red[tid + s];
        __syncthreads();
    }
    if (tid == 0) out[0] = red[0] * (1.0f / (float)B);
}

extern "C" void kernel_launch(void* const* d_in, const int* in_sizes, int n_in,
                              void* d_out, int out_size)
{
    const float* em     = (const float*)d_in[0];
    const int*   labels = (const int*)  d_in[1];
    const int*   mask   = (const int*)  d_in[2];
    const float* trans  = (const float*)d_in[3];
    const float* startt = (const float*)d_in[4];
    const float* endt   = (const float*)d_in[5];
    float* out = (float*)d_out;

    crf_fwd_kernel<<<B / 2, 64>>>(em, mask, trans, startt, endt);
    crf_gold_kernel<<<B, 256>>>(em, labels, mask, trans, startt, endt);
    crf_final_kernel<<<1, 512>>>(out);
}